// round 17
// baseline (speedup 1.0000x reference)
#include <cuda_runtime.h>

#define T_DATA 20000
#define TOFF   256
#define NXI    20400   // g_INT2 rows: TOFF + 20000 + pad
#define TILE   68      // k34 outputs per block; 295*68 = 20060 >= 20000
#define NB34   295

// ---------------- device scratch ----------------
__device__ float2   g_INT2[NXI * 12];    // [x][s] = (IN_e, IN_i), x = TOFF + t
__device__ float4   g_KER4[12 * 200];    // (kes, kis, ken, kin) per (s,k)
__device__ unsigned g_CTBE[64 * 12];     // permuted bit layout (matches k1f ballots)
__device__ unsigned g_CTBI[16 * 12];

__device__ __forceinline__ float sigmoidf_(float x) {
    return 1.0f / (1.0f + __expf(-x));
}

// packed f32x2 helpers (Blackwell)
#define FMA2(acc, a, b) \
    asm("fma.rn.f32x2 %0, %1, %2, %3;" : "=l"(acc) : "l"(a), "l"(b), "l"(acc))
#define PACK2(out, lo, hi) \
    asm("mov.b64 %0, {%1, %2};" : "=l"(out) : "f"(lo), "f"(hi))
#define UNPACK2(lo, hi, in) \
    asm("mov.b64 {%0, %1}, %2;" : "=f"(lo), "=f"(hi) : "l"(in))

// ---------------- K0a: pack C_syn via coalesced float4 + ballots -------------
__global__ void __launch_bounds__(960) k0a(const float4* __restrict__ Ce4,
                                           const float4* __restrict__ Ci4) {
    int warp = threadIdx.x >> 5, lane = threadIdx.x & 31;
    int gw = blockIdx.x * 30 + warp;                 // 0..239
    if (gw < 192) {                                   // E: 16 chunks x 12 subunits
        int w = gw / 12, s = gw % 12;
        int f = w * 32 + lane;
        float4 v = (f < 500) ? __ldg(Ce4 + s * 500 + f)
                             : make_float4(0.f, 0.f, 0.f, 0.f);
        unsigned m0 = __ballot_sync(0xffffffffu, v.x != 0.f);
        unsigned m1 = __ballot_sync(0xffffffffu, v.y != 0.f);
        unsigned m2 = __ballot_sync(0xffffffffu, v.z != 0.f);
        unsigned m3 = __ballot_sync(0xffffffffu, v.w != 0.f);
        if (lane == 0) {
            g_CTBE[(4 * w + 0) * 12 + s] = m0;
            g_CTBE[(4 * w + 1) * 12 + s] = m1;
            g_CTBE[(4 * w + 2) * 12 + s] = m2;
            g_CTBE[(4 * w + 3) * 12 + s] = m3;
        }
    } else if (gw < 240) {                            // I: 4 chunks x 12 subunits
        int j = gw - 192;
        int w = j / 12, s = j % 12;
        int f = w * 32 + lane;
        float4 v = (f < 125) ? __ldg(Ci4 + s * 125 + f)
                             : make_float4(0.f, 0.f, 0.f, 0.f);
        unsigned m0 = __ballot_sync(0xffffffffu, v.x != 0.f);
        unsigned m1 = __ballot_sync(0xffffffffu, v.y != 0.f);
        unsigned m2 = __ballot_sync(0xffffffffu, v.z != 0.f);
        unsigned m3 = __ballot_sync(0xffffffffu, v.w != 0.f);
        if (lane == 0) {
            g_CTBI[(4 * w + 0) * 12 + s] = m0;
            g_CTBI[(4 * w + 1) * 12 + s] = m1;
            g_CTBI[(4 * w + 2) * 12 + s] = m2;
            g_CTBI[(4 * w + 3) * 12 + s] = m3;
        }
    }
}

__device__ __forceinline__ float coef1(const float* __restrict__ W,
                                       const float* __restrict__ D,
                                       int s, int c, float t) {
    float ts = fmaxf(t - expf(D[s * 2 + c]), 0.f);
    float acc = 0.f;
    #pragma unroll
    for (int b = 0; b < 3; ++b) {
        float tau = expf(0.5f * (float)b);
        float tt  = ts / tau;
        acc += W[s * 6 + b * 2 + c] * tt * expf(-tt);
    }
    return acc;
}

// ---------------- K1f: fused bit-pack + popcount GEMM (round-9 proven) -------
__global__ void __launch_bounds__(256) k1f(const float4* __restrict__ Se4,
                                           const float4* __restrict__ Si4,
                                           const float* __restrict__ Wss,
                                           const float* __restrict__ Wns,
                                           const float* __restrict__ Dss,
                                           const float* __restrict__ Dns) {
    if (blockIdx.x >= 2500) {
        int gid = (blockIdx.x - 2500) * 256 + threadIdx.x;
        if (gid < 2400) {
            int s = gid / 200, k = gid % 200;
            float t = (float)k;
            float4 o;
            o.x = coef1(Wss, Dss, s, 0, t);
            o.y = coef1(Wss, Dss, s, 1, t);
            o.z = coef1(Wns, Dns, s, 0, t);
            o.w = coef1(Wns, Dns, s, 1, t);
            g_KER4[gid] = o;
        } else if (gid < 5472) {
            g_INT2[gid - 2400] = make_float2(0.f, 0.f);   // zero pad x < 256
        }
        return;
    }
    __shared__ unsigned sCE[768], sCI[192];
    int tid = threadIdx.x;
    for (int i = tid; i < 768; i += 256) sCE[i] = g_CTBE[i];
    if (tid < 192) sCI[tid] = g_CTBI[tid];
    __syncthreads();

    int lane = tid & 31;
    int row  = blockIdx.x * 8 + (tid >> 5);
    const float4* rE = Se4 + (size_t)row * 500;
    const float4* rI = Si4 + (size_t)row * 125;
    int lc = (lane < 12) ? lane : 0;
    int accE = 0, accI = 0;
    const float4 z4 = make_float4(0.f, 0.f, 0.f, 0.f);

    float4 vb[4];
    #pragma unroll
    for (int j = 0; j < 4; ++j) vb[j] = __ldg(rE + j * 32 + lane);

    #pragma unroll
    for (int w = 0; w < 16; ++w) {
        float4 v = vb[w & 3];
        int wn = w + 4;
        if (wn < 16) {
            int f = wn * 32 + lane;
            vb[w & 3] = (f < 500) ? __ldg(rE + f) : z4;
        } else {
            int f = (wn - 16) * 32 + lane;
            vb[w & 3] = (f < 125) ? __ldg(rI + f) : z4;
        }
        unsigned m0 = __ballot_sync(0xffffffffu, v.x != 0.f);
        unsigned m1 = __ballot_sync(0xffffffffu, v.y != 0.f);
        unsigned m2 = __ballot_sync(0xffffffffu, v.z != 0.f);
        unsigned m3 = __ballot_sync(0xffffffffu, v.w != 0.f);
        int b = w * 48 + lc;
        accE += __popc(m0 & sCE[b]);
        accE += __popc(m1 & sCE[b + 12]);
        accE += __popc(m2 & sCE[b + 24]);
        accE += __popc(m3 & sCE[b + 36]);
    }
    #pragma unroll
    for (int w = 0; w < 4; ++w) {
        float4 v = vb[w];
        unsigned m0 = __ballot_sync(0xffffffffu, v.x != 0.f);
        unsigned m1 = __ballot_sync(0xffffffffu, v.y != 0.f);
        unsigned m2 = __ballot_sync(0xffffffffu, v.z != 0.f);
        unsigned m3 = __ballot_sync(0xffffffffu, v.w != 0.f);
        int b = w * 48 + lc;
        accI += __popc(m0 & sCI[b]);
        accI += __popc(m1 & sCI[b + 12]);
        accI += __popc(m2 & sCI[b + 24]);
        accI += __popc(m3 & sCI[b + 36]);
    }
    if (lane < 12)
        g_INT2[(TOFF + row) * 12 + lane] = make_float2((float)accE, (float)accI);
}

// ---------------- K34 v4: occupancy-2 conv + cascade ------------------------
// 295 blocks x 68 t, 384 threads, 2 blocks/SM. warp = subunit: 200 taps,
// 3 outputs/lane (cols 80 = TILE + 12 halo), sliding reg window + f32x2.
// Two co-resident blocks hide each other's barriers and load latencies.
#define SS_OFF   0        // float [12*80] syn_s
#define SNS_OFF  960      // float [12*80] syn_ns
#define XNO_OFF  1920     // float [12*80] cascade levels
#define SOUT_OFF 2880     // float [68*35] = 2380
#define BUFSZ    6720     // floats; sIN (280*12 float2 = 6720 floats) aliases 0

__global__ void __launch_bounds__(384, 2) k34(const float* __restrict__ Cden,
                                              const float* __restrict__ Ths,
                                              const float* __restrict__ Thns,
                                              const float* __restrict__ Wssub,
                                              const float* __restrict__ Wnssub,
                                              float* __restrict__ out) {
    __shared__ __align__(16) float buf[BUFSZ];
    __shared__ float cwns[144], cds[144];
    __shared__ float ths[12], thns[12], ws[12], wns[12];
    int tid = threadIdx.x;
    int t0  = blockIdx.x * TILE;

    if (tid < 144) {
        float c = Cden[tid];
        cds [tid] = c;
        cwns[tid] = c * Wnssub[tid % 12];
    }
    if (tid >= 160 && tid < 172) {
        int q = tid - 160;
        ths [q] = Ths[q];
        thns[q] = Thns[q];
        ws  [q] = Wssub[q];
        wns [q] = Wnssub[q];
    }

    // stage IN window: sIN[s][xx] = IN at t = t0 - 212 + xx, xx in [0,280)
    float2* sIN = (float2*)buf;                        // [s][xx], pitch 280
    {
        int base = (TOFF + t0 - 212) * 12;
        for (int i = tid; i < 3360; i += 384) {        // 280 * 12, coalesced
            int xx = i / 12, s = i % 12;
            sIN[s * 280 + xx] = g_INT2[base + i];
        }
    }
    __syncthreads();

    // conv: warp = subunit; lane owns outputs m = 3*lane + j (j<3, m<80).
    // Output m, tap k needs xx = m + 200 - k.
    int warp = tid >> 5, lane = tid & 31;
    int s = warp;
    int mbase = 3 * lane;
    const unsigned long long* row =
        (const unsigned long long*)(sIN + s * 280);
    unsigned long long W0, W1, W2;
    unsigned long long aS0 = 0, aS1 = 0, aS2 = 0;
    unsigned long long aN0 = 0, aN1 = 0, aN2 = 0;
    W0 = row[min(mbase + 200, 279)];
    W1 = row[min(mbase + 201, 279)];
    W2 = row[min(mbase + 202, 279)];
    const float4* kp = g_KER4 + s * 200;
    #pragma unroll 5
    for (int k = 0; k < 200; ++k) {
        float4 kc = __ldg(kp + k);
        unsigned long long cs, cn;
        PACK2(cs, kc.x, kc.y);
        PACK2(cn, kc.z, kc.w);
        FMA2(aS0, W0, cs); FMA2(aN0, W0, cn);
        FMA2(aS1, W1, cs); FMA2(aN1, W1, cn);
        FMA2(aS2, W2, cs); FMA2(aN2, W2, cn);
        W2 = W1; W1 = W0;
        W0 = row[min(max(mbase + 199 - k, 0), 279)];   // next incoming
    }
    __syncthreads();                                   // sIN dead; buf reusable

    // write syn into SS / SNS (single warp per subunit: no combine needed)
    {
        float lo, hi;
        #pragma unroll
        for (int j = 0; j < 3; ++j) {
            int m = mbase + j;
            if (m < 80) {
                unsigned long long vS, vN;
                switch (j) {
                    case 0: vS = aS0; vN = aN0; break;
                    case 1: vS = aS1; vN = aN1; break;
                    default: vS = aS2; vN = aN2; break;
                }
                UNPACK2(lo, hi, vS); buf[SS_OFF  + s * 80 + m] = lo + hi;
                UNPACK2(lo, hi, vN); buf[SNS_OFF + s * 80 + m] = lo + hi;
            }
        }
    }
    __syncthreads();

    // cascade: 12 lower-triangular levels over cols m = 0..79
    #pragma unroll
    for (int i = 0; i < 12; ++i) {
        if (tid < 80) {
            int t = t0 - 12 + tid;
            float v = 0.f;
            if (t >= 0) {
                float x = buf[SNS_OFF + i * 80 + tid] + thns[i];
                #pragma unroll
                for (int j = 0; j < i; ++j) {
                    float yp = (tid > 0) ? buf[XNO_OFF + j * 80 + tid - 1] : 0.f;
                    x = fmaf(cwns[i * 12 + j], yp, x);
                }
                v = sigmoidf_(x);
            }
            buf[XNO_OFF + i * 80 + tid] = v;
        }
        __syncthreads();
    }

    // epilogue: per-t outputs
    if (tid < TILE) {
        int t = t0 + tid, h = tid + 12;
        if (t < T_DATA) {
            float ysp[12];
            if (t == 0) {
                #pragma unroll
                for (int j = 0; j < 12; ++j) ysp[j] = 0.f;
            } else {
                float x0 = buf[SS_OFF + 0 * 80 + tid + 11] + ths[0];
                ysp[0] = sigmoidf_(x0) * ws[0];
                #pragma unroll
                for (int j = 1; j < 12; ++j)
                    ysp[j] = buf[XNO_OFF + j * 80 + h - 1] * ws[j];
            }
            float* o = buf + SOUT_OFF + tid * 35;
            #pragma unroll
            for (int i = 0; i < 12; ++i) {
                float xs = buf[SS_OFF + i * 80 + tid + 12] + ths[i];
                #pragma unroll
                for (int j = 0; j < i; ++j) xs = fmaf(cds[i * 12 + j], ysp[j], xs);
                float sg  = sigmoidf_(xs);
                float xti = buf[XNO_OFF + i * 80 + h];
                o[i]      = (i == 0) ? sg * ws[0] : xti * ws[i];
                o[12 + i] = xti * wns[i];
                if (i >= 1) o[24 + i - 1] = sg;
            }
        }
    }
    __syncthreads();
    int nvalid = T_DATA - t0; if (nvalid > TILE) nvalid = TILE;
    float* ob = out + (size_t)t0 * 35;
    if (nvalid == TILE) {
        float4* o4 = (float4*)ob;                      // t0*35 = bid*2380, %4 == 0
        const float4* sb = (const float4*)(buf + SOUT_OFF);
        for (int i = tid; i < 595; i += 384) o4[i] = sb[i];
    } else if (nvalid > 0) {
        int nf = nvalid * 35;
        for (int i = tid; i < nf; i += 384) ob[i] = buf[SOUT_OFF + i];
    }
}

// ---------------- launch ----------------
extern "C" void kernel_launch(void* const* d_in, const int* in_sizes, int n_in,
                              void* d_out, int out_size) {
    const float* S_e      = (const float*)d_in[0];
    const float* S_i      = (const float*)d_in[1];
    const float* C_syn_e  = (const float*)d_in[2];
    const float* C_syn_i  = (const float*)d_in[3];
    const float* C_den    = (const float*)d_in[4];
    const float* W_s_syn  = (const float*)d_in[5];
    const float* W_ns_syn = (const float*)d_in[6];
    const float* D_s      = (const float*)d_in[7];
    const float* D_ns     = (const float*)d_in[8];
    const float* Theta_s  = (const float*)d_in[9];
    const float* Theta_ns = (const float*)d_in[10];
    const float* W_s_sub  = (const float*)d_in[11];
    const float* W_ns_sub = (const float*)d_in[12];
    float* out = (float*)d_out;

    k0a<<<8, 960>>>((const float4*)C_syn_e, (const float4*)C_syn_i);
    k1f<<<2522, 256>>>((const float4*)S_e, (const float4*)S_i,
                       W_s_syn, W_ns_syn, D_s, D_ns);
    k34<<<NB34, 384>>>(C_den, Theta_s, Theta_ns, W_s_sub, W_ns_sub, out);
}